// round 15
// baseline (speedup 1.0000x reference)
#include <cuda_runtime.h>
#include <cstdint>
#include <math.h>

#define NAq 1152
#define NDq 736
#define NPq 512

#define QANG 288               // base angles; classes j are rows a+288j
#define SPLIT 4
#define APB (QANG / SPLIT)     // 72 quad-groups per bp block
#define CH 2                   // quad-groups per chunk
#define GRP2 (NDq * 4)         // float2 per quad-group (interleaved) (2944)
#define CHP (CH * GRP2)        // float2 per chunk (5888)
#define CHP4 (CHP / 2)         // float4 per chunk (2944)
#define BP_DSMEM (2 * CHP * 8) // dynamic smem bytes (94208)
#define NPART SPLIT            // 4 partial planes

// ---- geometry in double (compile-time folded) ----
#define VOXd (1.0 / 0.7)
#define Dd   (VOXd * 595.0)
#define DDd  (VOXd * 490.6)
#define DUd  (VOXd * 1.2858)
#define DSDd (Dd + DDd)

// ---- device scratch (static allocation: allowed) ----
__device__ float  g_filt[1025];
__device__ float  g_hext[1472];          // h[|i-735|] * pi/(2*NA)
__device__ float2 g_trig2[NAq];          // (cos, sin)
__device__ float2 g_fpq[QANG * NDq * 4]; // interleaved: [qa][n][class] (v, dv)
__device__ float  g_part[NPART][NPq * NPq];

__device__ __forceinline__ float frcp(float x) {
    float r;
    asm("rcp.approx.f32 %0, %1;" : "=f"(r) : "f"(x));
    return r;
}
__device__ __forceinline__ void cpasync16(unsigned int s, const void* g) {
    asm volatile("cp.async.cg.shared.global [%0], [%1], 16;" :: "r"(s), "l"(g));
}
__device__ __forceinline__ void cpasync_commit() {
    asm volatile("cp.async.commit_group;");
}
__device__ __forceinline__ void cpasync_wait0() {
    asm volatile("cp.async.wait_group 0;");
}

// ---------------------------------------------------------------------------
// Launch #1: FILT[k] (blocks 0..1024) + angle trig (blocks 1025..1033).
// ---------------------------------------------------------------------------
__global__ void __launch_bounds__(128) filt_kernel() {
    int bid = blockIdx.x;
    int tid = threadIdx.x;
    if (bid >= 1025) {
        int a = (bid - 1025) * 128 + tid;        // 9*128 = 1152
        double beta = 2.0 * M_PI * (double)a / (double)NAq + M_PI / 2.0;
        g_trig2[a] = make_float2((float)cos(beta), (float)sin(beta));
        return;
    }
    __shared__ double red[128];
    int k = bid;
    double s = 0.0;
#pragma unroll
    for (int j = 0; j < 4; j++) {
        int m = tid + j * 128;
        int jj = 2 * m + 1;
        float c = cospif((float)((k * jj) & 2047) * (1.0f / 1024.0f));
        s += (double)(c / ((float)jj * (float)jj));
    }
    red[tid] = s;
    __syncthreads();
    for (int w = 64; w > 0; w >>= 1) {
        if (tid < w) red[tid] += red[tid + w];
        __syncthreads();
    }
    if (tid == 0) {
        double four = 0.5 - (4.0 / (M_PI * M_PI)) * red[0];
        if (k > 0) {
            double om = M_PI * (double)k / 2048.0;
            four *= sin(om) / om;
        }
        g_filt[k] = (float)four;
    }
}

// ---------------------------------------------------------------------------
// Launch #2: h[d] = irfft(FILT)[d]. One block per d, 128 threads + reduction.
// ---------------------------------------------------------------------------
__global__ void __launch_bounds__(128) hker_kernel() {
    __shared__ double red[128];
    int d = blockIdx.x;
    int tid = threadIdx.x;
    double s = 0.0;
    for (int k = 1 + tid; k <= 1023; k += 128) {
        s += (double)g_filt[k] * (double)cospif((float)((k * d) & 2047) * (1.0f / 1024.0f));
    }
    red[tid] = s;
    __syncthreads();
    for (int w = 64; w > 0; w >>= 1) {
        if (tid < w) red[tid] += red[tid + w];
        __syncthreads();
    }
    if (tid == 0) {
        double t = (double)g_filt[0] + (double)g_filt[1024] * ((d & 1) ? -1.0 : 1.0)
                 + 2.0 * red[0];
        float h = (float)(t * (1.0 / 2048.0) * (M_PI / (2.0 * (double)NAq)));
        g_hext[735 - d] = h;
        g_hext[735 + d] = h;
    }
}

// ---------------------------------------------------------------------------
// Launch #3: filtering as linear convolution, 2 rows/block (576 blocks for
// occupancy); emits (v, dv) into the class-interleaved quad layout.
// ---------------------------------------------------------------------------
#define RB 2
__global__ void __launch_bounds__(256) conv_kernel(const float* __restrict__ sino) {
    __shared__ float s_s[RB][NDq];
    __shared__ float s_h[1536];
    int tid = threadIdx.x;
    int row0 = blockIdx.x * RB;
#pragma unroll
    for (int r = 0; r < RB; r++)
        for (int i = tid; i < NDq; i += 256)
            s_s[r][i] = sino[(row0 + r) * NDq + i];
    for (int i = tid; i < 1536; i += 256) s_h[i] = (i < 1471) ? g_hext[i] : 0.0f;
    __syncthreads();

    float acc[RB][3] = {};
    const float* h0 = s_h + tid + 735;
#pragma unroll 4
    for (int k = 0; k < NDq; k++) {
        float hv0 = h0[-k];
        float hv1 = h0[256 - k];
        float hv2 = h0[512 - k];
#pragma unroll
        for (int r = 0; r < RB; r++) {
            float sv = s_s[r][k];
            acc[r][0] = fmaf(sv, hv0, acc[r][0]);
            acc[r][1] = fmaf(sv, hv1, acc[r][1]);
            acc[r][2] = fmaf(sv, hv2, acc[r][2]);
        }
    }
    __syncthreads();
#pragma unroll
    for (int r = 0; r < RB; r++) {
        s_s[r][tid] = acc[r][0];
        s_s[r][tid + 256] = acc[r][1];
        if (tid < NDq - 512) s_s[r][tid + 512] = acc[r][2];
    }
    __syncthreads();
#pragma unroll
    for (int r = 0; r < RB; r++) {
        int a   = row0 + r;
        int qa  = a % QANG;
        int cls = a / QANG;
        float2* dst = g_fpq + qa * (NDq * 4) + cls;
        for (int i = tid; i < NDq; i += 256) {
            float v = s_s[r][i];
            float vn = (i < NDq - 1) ? s_s[r][i + 1] : v;
            dst[i * 4] = make_float2(v, vn - v);
        }
    }
}

// ---------------------------------------------------------------------------
// Launch #4 (PROFILED SLOT): fan-beam backprojection, FULL 4-fold symmetry,
// class-interleaved gathers. Quad-group {A, A+288, A+576, A+864}: one
// (U, frac, weight) serves 4 gathers, now fetched as TWO LDS.128 from the
// interleaved [n][class] layout (was 4x LDS.64). Paired reciprocals:
// 1/(D-+pd) = (D+-pd) * rcp(D^2-pd^2) -> 2 MUFU per quad instead of 4.
// Grid (4, 16, 4): quadrant x,y in [256,512), 64x16 tiles, 512 thr, 2 y/thr.
// ---------------------------------------------------------------------------
__global__ void __launch_bounds__(512, 2) bp_kernel() {
    extern __shared__ __align__(16) float2 dsm[];   // 2 chunks x CHP float2
    __shared__ float2 s_tr[2][CH];
    int tid = threadIdx.x;
    int z   = blockIdx.z;
    int w   = tid >> 5;
    int l   = tid & 31;
    int x   = 256 + blockIdx.x * 64 + (w & 1) * 32 + l;
    int y0  = 256 + blockIdx.y * 16 + (w >> 1) * 2;

    float xs  = (float)x  - 255.5f;
    float ys0 = (float)y0 - 255.5f;

    const float Df  = (float)Dd;
    const float Df2 = (float)(Dd * Dd);
    const float Kf  = (float)(DSDd / DUd);

    // per-warp classification (radius bound; identical for all 4 bases)
    int wx0 = 256 + blockIdx.x * 64 + (w & 1) * 32;
    float mx = fmaxf(fabsf((float)wx0 - 255.5f), fabsf((float)wx0 + 31.0f - 255.5f));
    float my = fabsf((float)y0 + 1.0f - 255.5f);
    float rm = sqrtf(mx * mx + my * my);
    bool fast = (Kf * rm) < (366.9f * (Df - rm));

    unsigned int sb0a = (unsigned int)__cvta_generic_to_shared(&dsm[0]);
    unsigned int sb1a = (unsigned int)__cvta_generic_to_shared(&dsm[CHP]);
    int abase = z * APB;

    // preload chunk 0 (contiguous copy of CH interleaved quad-groups)
    {
        const float4* src = (const float4*)(g_fpq + abase * GRP2);
#pragma unroll
        for (int j = 0; j < 6; j++) {
            int idx = tid + j * 512;
            if (idx < CHP4) cpasync16(sb0a + idx * 16, src + idx);
        }
    }
    if (tid < CH) s_tr[0][tid] = g_trig2[abase + tid];
    cpasync_commit();
    cpasync_wait0();
    __syncthreads();

    float acc[8];                                    // [partner*2 + i]
#pragma unroll
    for (int i = 0; i < 8; i++) acc[i] = 0.0f;

    const int NCHb = APB / CH;                       // 36
    for (int c = 0; c < NCHb; c++) {
        if (c + 1 < NCHb) {
            unsigned int dsts = (c & 1) ? sb0a : sb1a;
            const float4* src = (const float4*)(g_fpq + (abase + (c + 1) * CH) * GRP2);
#pragma unroll
            for (int j = 0; j < 6; j++) {
                int idx = tid + j * 512;
                if (idx < CHP4) cpasync16(dsts + idx * 16, src + idx);
            }
            if (tid < CH) s_tr[(c + 1) & 1][tid] = g_trig2[abase + (c + 1) * CH + tid];
        }
        cpasync_commit();

        const float2* buf = (c & 1) ? (dsm + CHP) : dsm;

#pragma unroll
        for (int g = 0; g < CH; g++) {
            float2 t2 = s_tr[c & 1][g];
            float cb = t2.x, sb = t2.y;
            // entry (n, class) at rowq[n*4 + class]; n in [2,737] maps via -8
            const float2* rowq = buf + g * GRP2 - 8;

            // shared geometry: pd = pdot(A,p), pq = pe(A,p)
            float pd  = fmaf(xs, cb, ys0 * sb);
            float pq  = fmaf(ys0, cb, -xs * sb);
            float pdK = pd * Kf;
            float pqK = pq * Kf;
            float cbK = cb * Kf, sbK = sb * Kf;
            // paired reciprocals: 2 MUFU serve all 4 bases
            float inv02 = frcp(fmaf(pd, -pd, Df2));
            float inv13 = frcp(fmaf(pq, -pq, Df2));

#pragma unroll
            for (int b = 0; b < 4; b++) {
                // base A+288b: den/peK/derivatives are sign-swaps (b static)
                float peK  = (b == 0) ? pqK : (b == 1) ? -pdK
                           : (b == 2) ? -pqK : pdK;
                float cbKB = (b == 0) ? cbK : (b == 1) ? -sbK
                           : (b == 2) ? -cbK : sbK;         // d(peK)/dy
                float sbB  = (b == 0) ? sb : (b == 1) ? cb
                           : (b == 2) ? -sb : -cb;          // d(den)/dy = -sbB
                float r0   = (b == 0) ? (Df + pd) * inv02
                           : (b == 1) ? (Df + pq) * inv13
                           : (b == 2) ? (Df - pd) * inv02
                           :            (Df - pq) * inv13;  // 1/den_b
                float e  = sbB * r0;
                float r  = r0;

                if (fast) {
#pragma unroll
                    for (int i = 0; i < 2; i++) {
                        float U  = fmaf(peK, r, 369.5f);     // iu+2 in (2.6,736.4)
                        float M  = U + 8388607.5f;
                        int   n  = __float_as_int(M) & 0x3FF;
                        float fr = U - (M - 8388608.0f);
                        float wgt = r * r;
                        const float4* pp = (const float4*)(rowq + (n << 2));
                        float4 q01 = pp[0];                  // classes 0,1
                        float4 q23 = pp[1];                  // classes 2,3
                        float vx[4] = {q01.x, q01.z, q23.x, q23.z};
                        float vy[4] = {q01.y, q01.w, q23.y, q23.w};
#pragma unroll
                        for (int j = 0; j < 4; j++) {
                            int cc = (b + j) & 3;
                            acc[2 * j + i] = fmaf(wgt, fmaf(fr, vy[cc], vx[cc]),
                                                  acc[2 * j + i]);
                        }
                        if (i == 0) {                        // advance dy=1
                            float f = fmaf(e, e, e);         // t + t^2
                            r = fmaf(r0, f, r0);
                            peK += cbKB;
                        }
                    }
                } else {
#pragma unroll
                    for (int i = 0; i < 2; i++) {
                        float U  = fmaf(peK, r, 369.5f);
                        float Uc = fminf(fmaxf(U, 2.0f), 736.999f);
                        float M  = Uc + 8388607.5f;
                        int   n  = __float_as_int(M) & 0x3FF;  // [2, 737]
                        float fr = Uc - (M - 8388608.0f);
                        bool  ok = (U >= 2.0f) && (U < 737.0f);
                        float wgt = ok ? r * r : 0.0f;
                        const float4* pp = (const float4*)(rowq + (n << 2));
                        float4 q01 = pp[0];
                        float4 q23 = pp[1];
                        float vx[4] = {q01.x, q01.z, q23.x, q23.z};
                        float vy[4] = {q01.y, q01.w, q23.y, q23.w};
#pragma unroll
                        for (int j = 0; j < 4; j++) {
                            int cc = (b + j) & 3;
                            acc[2 * j + i] = fmaf(wgt, fmaf(fr, vy[cc], vx[cc]),
                                                  acc[2 * j + i]);
                        }
                        if (i == 0) {
                            float f = fmaf(e, e, e);
                            r = fmaf(r0, f, r0);
                            peK += cbKB;
                        }
                    }
                }
            }
        }

        cpasync_wait0();
        __syncthreads();
    }

    // Four rotated writes to plane z (disjoint quadrants tiling the image).
    float* P = g_part[z];
    int xm = (NPq - 1) - x;
#pragma unroll
    for (int i = 0; i < 2; i++) {
        int yy = y0 + i;
        int ym = (NPq - 1) - yy;
        P[yy * NPq + x]  = acc[0 + i];
        P[x * NPq + ym]  = acc[2 + i];
        P[ym * NPq + xm] = acc[4 + i];
        P[xm * NPq + yy] = acc[6 + i];
    }
}

// ---------------------------------------------------------------------------
// Launch #5: sum the 4 partial planes + HU normalization.
// ---------------------------------------------------------------------------
__global__ void __launch_bounds__(128) reduce_kernel(float* __restrict__ out) {
    const float A = (float)((Dd * Dd) * (1000.0 / 0.0192) / 4096.0);
    const float B = (float)(24.0 / 4096.0);
    int idx = blockIdx.x * 128 + threadIdx.x;      // float4 index
    float sx = 0.f, sy = 0.f, sz = 0.f, sw = 0.f;
#pragma unroll
    for (int p = 0; p < NPART; p++) {
        float4 v = ((const float4*)g_part[p])[idx];
        sx += v.x; sy += v.y; sz += v.z; sw += v.w;
    }
    float4 o;
    o.x = fmaf(A, sx, B);
    o.y = fmaf(A, sy, B);
    o.z = fmaf(A, sz, B);
    o.w = fmaf(A, sw, B);
    ((float4*)out)[idx] = o;
}

// ---------------------------------------------------------------------------
extern "C" void kernel_launch(void* const* d_in, const int* in_sizes, int n_in,
                              void* d_out, int out_size) {
    const float* sino = (const float*)d_in[0];
    float* out = (float*)d_out;

    cudaFuncSetAttribute(bp_kernel,
                         cudaFuncAttributeMaxDynamicSharedMemorySize, BP_DSMEM);

    filt_kernel<<<1034, 128>>>();           // FILT (1025 blocks) + trig (9)
    hker_kernel<<<NDq, 128>>>();            // spatial filter kernel
    conv_kernel<<<NAq / RB, 256>>>(sino);   // filtered sinogram -> interleaved
    dim3 grid(4, 16, SPLIT);                // 64x16 quadrant tiles x 4 splits
    bp_kernel<<<grid, 512, BP_DSMEM>>>();   // <-- 4th launch (profiled slot)
    reduce_kernel<<<NPq * NPq / 4 / 128, 128>>>(out);
}

// round 16
// speedup vs baseline: 1.3387x; 1.3387x over previous
#include <cuda_runtime.h>
#include <cstdint>
#include <math.h>

#define NAq 1152
#define NDq 736
#define NPq 512

#define QANG 288               // base angles; rows a+288j staged per quad-group
#define SPLIT 4
#define APB (QANG / SPLIT)     // 72 quad-groups per bp block
#define CH 2                   // quad-groups per chunk
#define RPC (CH * 4)           // rows per chunk (8)
#define CHP (RPC * NDq)        // float2 per chunk (5888)
#define CHP4 (CHP / 2)         // float4 per chunk (2944)
#define ROW4 (NDq / 2)         // float4 per row (368)
#define BP_DSMEM (2 * CHP * 8) // dynamic smem bytes (94208)
#define NPART SPLIT            // 4 partial planes

// ---- geometry in double (compile-time folded) ----
#define VOXd (1.0 / 0.7)
#define Dd   (VOXd * 595.0)
#define DDd  (VOXd * 490.6)
#define DUd  (VOXd * 1.2858)
#define DSDd (Dd + DDd)

// ---- device scratch (static allocation: allowed) ----
__device__ float  g_filt[1025];
__device__ float  g_hext[1472];          // h[|i-735|] * pi/(2*NA)
__device__ float2 g_trig2[NAq];          // (cos, sin)
__device__ float2 g_fp2[NAq * NDq];      // filtered rows as (v, v_next - v)
__device__ float  g_part[NPART][NPq * NPq];

__device__ __forceinline__ float frcp(float x) {
    float r;
    asm("rcp.approx.f32 %0, %1;" : "=f"(r) : "f"(x));
    return r;
}
__device__ __forceinline__ void cpasync16(unsigned int s, const void* g) {
    asm volatile("cp.async.cg.shared.global [%0], [%1], 16;" :: "r"(s), "l"(g));
}
__device__ __forceinline__ void cpasync_commit() {
    asm volatile("cp.async.commit_group;");
}
__device__ __forceinline__ void cpasync_wait0() {
    asm volatile("cp.async.wait_group 0;");
}

// ---------------------------------------------------------------------------
// Launch #1: FILT[k] (blocks 0..1024) + angle trig (blocks 1025..1033).
// ---------------------------------------------------------------------------
__global__ void __launch_bounds__(128) filt_kernel() {
    int bid = blockIdx.x;
    int tid = threadIdx.x;
    if (bid >= 1025) {
        int a = (bid - 1025) * 128 + tid;        // 9*128 = 1152
        double beta = 2.0 * M_PI * (double)a / (double)NAq + M_PI / 2.0;
        g_trig2[a] = make_float2((float)cos(beta), (float)sin(beta));
        return;
    }
    __shared__ double red[128];
    int k = bid;
    double s = 0.0;
#pragma unroll
    for (int j = 0; j < 4; j++) {
        int m = tid + j * 128;
        int jj = 2 * m + 1;
        float c = cospif((float)((k * jj) & 2047) * (1.0f / 1024.0f));
        s += (double)(c / ((float)jj * (float)jj));
    }
    red[tid] = s;
    __syncthreads();
    for (int w = 64; w > 0; w >>= 1) {
        if (tid < w) red[tid] += red[tid + w];
        __syncthreads();
    }
    if (tid == 0) {
        double four = 0.5 - (4.0 / (M_PI * M_PI)) * red[0];
        if (k > 0) {
            double om = M_PI * (double)k / 2048.0;
            four *= sin(om) / om;
        }
        g_filt[k] = (float)four;
    }
}

// ---------------------------------------------------------------------------
// Launch #2: h[d] = irfft(FILT)[d]. One block per d, 128 threads + reduction.
// ---------------------------------------------------------------------------
__global__ void __launch_bounds__(128) hker_kernel() {
    __shared__ double red[128];
    int d = blockIdx.x;
    int tid = threadIdx.x;
    double s = 0.0;
    for (int k = 1 + tid; k <= 1023; k += 128) {
        s += (double)g_filt[k] * (double)cospif((float)((k * d) & 2047) * (1.0f / 1024.0f));
    }
    red[tid] = s;
    __syncthreads();
    for (int w = 64; w > 0; w >>= 1) {
        if (tid < w) red[tid] += red[tid + w];
        __syncthreads();
    }
    if (tid == 0) {
        double t = (double)g_filt[0] + (double)g_filt[1024] * ((d & 1) ? -1.0 : 1.0)
                 + 2.0 * red[0];
        float h = (float)(t * (1.0 / 2048.0) * (M_PI / (2.0 * (double)NAq)));
        g_hext[735 - d] = h;
        g_hext[735 + d] = h;
    }
}

// ---------------------------------------------------------------------------
// Launch #3: filtering as linear convolution, 4 rows/block; (v, dv) pairs out.
// ---------------------------------------------------------------------------
#define RB 4
__global__ void __launch_bounds__(256) conv_kernel(const float* __restrict__ sino) {
    __shared__ float s_s[RB][NDq];
    __shared__ float s_h[1536];
    int tid = threadIdx.x;
    int row0 = blockIdx.x * RB;
#pragma unroll
    for (int r = 0; r < RB; r++)
        for (int i = tid; i < NDq; i += 256)
            s_s[r][i] = sino[(row0 + r) * NDq + i];
    for (int i = tid; i < 1536; i += 256) s_h[i] = (i < 1471) ? g_hext[i] : 0.0f;
    __syncthreads();

    float acc[RB][3] = {};
    const float* h0 = s_h + tid + 735;
#pragma unroll 4
    for (int k = 0; k < NDq; k++) {
        float hv0 = h0[-k];
        float hv1 = h0[256 - k];
        float hv2 = h0[512 - k];
#pragma unroll
        for (int r = 0; r < RB; r++) {
            float sv = s_s[r][k];
            acc[r][0] = fmaf(sv, hv0, acc[r][0]);
            acc[r][1] = fmaf(sv, hv1, acc[r][1]);
            acc[r][2] = fmaf(sv, hv2, acc[r][2]);
        }
    }
    __syncthreads();
#pragma unroll
    for (int r = 0; r < RB; r++) {
        s_s[r][tid] = acc[r][0];
        s_s[r][tid + 256] = acc[r][1];
        if (tid < NDq - 512) s_s[r][tid + 512] = acc[r][2];
    }
    __syncthreads();
#pragma unroll
    for (int r = 0; r < RB; r++) {
        float2* dst = g_fp2 + (row0 + r) * NDq;
        for (int i = tid; i < NDq; i += 256) {
            float v = s_s[r][i];
            float vn = (i < NDq - 1) ? s_s[r][i + 1] : v;
            dst[i] = make_float2(v, vn - v);
        }
    }
}

// ---------------------------------------------------------------------------
// Launch #4 (PROFILED SLOT): fan-beam backprojection, FULL 4-fold symmetry.
// Quad-group: bases {A, A+288, A+576, A+864} processed together; one
// (U, frac, weight) serves 4 gathers (separate per-row LDS.64 streams —
// compact lane footprint, R15's interleaved layout conflicted). Paired
// reciprocals: 1/(D-+pd) = (D+-pd)*rcp(D^2-pd^2) -> 2 MUFU/quad (was 4).
// Grid (4, 16, 4): quadrant x,y in [256,512), 64x16 tiles, 512 thr, 2 y/thr,
// acc[8]. Chunks: 2 quad-groups x 4 rows, cp.async double-buffered (94 KB).
// ---------------------------------------------------------------------------
__global__ void __launch_bounds__(512, 2) bp_kernel() {
    extern __shared__ __align__(16) float2 dsm[];   // 2 chunks x CHP float2
    __shared__ float2 s_tr[2][CH];
    int tid = threadIdx.x;
    int z   = blockIdx.z;
    int w   = tid >> 5;
    int l   = tid & 31;
    int x   = 256 + blockIdx.x * 64 + (w & 1) * 32 + l;
    int y0  = 256 + blockIdx.y * 16 + (w >> 1) * 2;

    float xs  = (float)x  - 255.5f;
    float ys0 = (float)y0 - 255.5f;

    const float Df  = (float)Dd;
    const float Df2 = (float)(Dd * Dd);
    const float Kf  = (float)(DSDd / DUd);

    // per-warp classification (radius bound; identical for all 4 bases)
    int wx0 = 256 + blockIdx.x * 64 + (w & 1) * 32;
    float mx = fmaxf(fabsf((float)wx0 - 255.5f), fabsf((float)wx0 + 31.0f - 255.5f));
    float my = fabsf((float)y0 + 1.0f - 255.5f);
    float rm = sqrtf(mx * mx + my * my);
    bool fast = (Kf * rm) < (366.9f * (Df - rm));

    unsigned int sb0a = (unsigned int)__cvta_generic_to_shared(&dsm[0]);
    unsigned int sb1a = (unsigned int)__cvta_generic_to_shared(&dsm[CHP]);
    int abase = z * APB;

    // preload chunk 0: smem row r = quad-group (r>>2), rotation class (r&3)
#pragma unroll
    for (int j = 0; j < 6; j++) {
        int idx = tid + j * 512;
        if (idx < CHP4) {
            int r = idx / ROW4;
            int o = idx - r * ROW4;
            int srow = abase + (r >> 2) + (r & 3) * QANG;
            cpasync16(sb0a + idx * 16, (const float4*)(g_fp2 + srow * NDq) + o);
        }
    }
    if (tid < CH) s_tr[0][tid] = g_trig2[abase + tid];
    cpasync_commit();
    cpasync_wait0();
    __syncthreads();

    float acc[8];                                    // [partner*2 + i]
#pragma unroll
    for (int i = 0; i < 8; i++) acc[i] = 0.0f;

    const int NCHb = APB / CH;                       // 36
    for (int c = 0; c < NCHb; c++) {
        if (c + 1 < NCHb) {
            unsigned int dsts = (c & 1) ? sb0a : sb1a;
            int gbase = abase + (c + 1) * CH;
#pragma unroll
            for (int j = 0; j < 6; j++) {
                int idx = tid + j * 512;
                if (idx < CHP4) {
                    int r = idx / ROW4;
                    int o = idx - r * ROW4;
                    int srow = gbase + (r >> 2) + (r & 3) * QANG;
                    cpasync16(dsts + idx * 16, (const float4*)(g_fp2 + srow * NDq) + o);
                }
            }
            if (tid < CH) s_tr[(c + 1) & 1][tid] = g_trig2[gbase + tid];
        }
        cpasync_commit();

        const float2* buf = (c & 1) ? (dsm + CHP) : dsm;

#pragma unroll
        for (int g = 0; g < CH; g++) {
            float2 t2 = s_tr[c & 1][g];
            float cb = t2.x, sb = t2.y;
            const float2* rowg = buf + (g * 4) * NDq - 2;

            // shared geometry for the quad: pd = pdot(A,p), pq = pe(A,p)
            float pd  = fmaf(xs, cb, ys0 * sb);
            float pq  = fmaf(ys0, cb, -xs * sb);
            float pdK = pd * Kf;
            float pqK = pq * Kf;
            float cbK = cb * Kf, sbK = sb * Kf;
            // paired reciprocals: 2 MUFU serve all 4 bases
            float inv02 = frcp(fmaf(pd, -pd, Df2));
            float inv13 = frcp(fmaf(pq, -pq, Df2));

#pragma unroll
            for (int b = 0; b < 4; b++) {
                // base A+288b: den/peK/derivatives are sign-swaps (b static)
                float peK  = (b == 0) ? pqK : (b == 1) ? -pdK
                           : (b == 2) ? -pqK : pdK;
                float cbKB = (b == 0) ? cbK : (b == 1) ? -sbK
                           : (b == 2) ? -cbK : sbK;         // d(peK)/dy
                float sbB  = (b == 0) ? sb : (b == 1) ? cb
                           : (b == 2) ? -sb : -cb;          // d(den)/dy = -sbB
                float r0   = (b == 0) ? (Df + pd) * inv02
                           : (b == 1) ? (Df + pq) * inv13
                           : (b == 2) ? (Df - pd) * inv02
                           :            (Df - pq) * inv13;  // 1/den_b
                float e  = sbB * r0;
                float r  = r0;
                // smem row offsets for partners j: row (b+j)&3
                const int o0 = ((b + 0) & 3) * NDq;
                const int o1 = ((b + 1) & 3) * NDq;
                const int o2 = ((b + 2) & 3) * NDq;
                const int o3 = ((b + 3) & 3) * NDq;

                if (fast) {
#pragma unroll
                    for (int i = 0; i < 2; i++) {
                        float U  = fmaf(peK, r, 369.5f);     // iu+2 in (2.6,736.4)
                        float M  = U + 8388607.5f;
                        int   n  = __float_as_int(M) & 0x3FF;
                        float fr = U - (M - 8388608.0f);
                        float wgt = r * r;
                        float2 v0 = rowg[n + o0];
                        float2 v1 = rowg[n + o1];
                        float2 v2 = rowg[n + o2];
                        float2 v3 = rowg[n + o3];
                        acc[0 + i] = fmaf(wgt, fmaf(fr, v0.y, v0.x), acc[0 + i]);
                        acc[2 + i] = fmaf(wgt, fmaf(fr, v1.y, v1.x), acc[2 + i]);
                        acc[4 + i] = fmaf(wgt, fmaf(fr, v2.y, v2.x), acc[4 + i]);
                        acc[6 + i] = fmaf(wgt, fmaf(fr, v3.y, v3.x), acc[6 + i]);
                        if (i == 0) {                        // advance dy=1
                            float f = fmaf(e, e, e);         // t + t^2
                            r = fmaf(r0, f, r0);
                            peK += cbKB;
                        }
                    }
                } else {
#pragma unroll
                    for (int i = 0; i < 2; i++) {
                        float U  = fmaf(peK, r, 369.5f);
                        float Uc = fminf(fmaxf(U, 2.0f), 736.999f);
                        float M  = Uc + 8388607.5f;
                        int   n  = __float_as_int(M) & 0x3FF;  // [2, 736]
                        float fr = Uc - (M - 8388608.0f);
                        bool  ok = (U >= 2.0f) && (U < 737.0f);
                        float wgt = ok ? r * r : 0.0f;
                        float2 v0 = rowg[n + o0];
                        float2 v1 = rowg[n + o1];
                        float2 v2 = rowg[n + o2];
                        float2 v3 = rowg[n + o3];
                        acc[0 + i] = fmaf(wgt, fmaf(fr, v0.y, v0.x), acc[0 + i]);
                        acc[2 + i] = fmaf(wgt, fmaf(fr, v1.y, v1.x), acc[2 + i]);
                        acc[4 + i] = fmaf(wgt, fmaf(fr, v2.y, v2.x), acc[4 + i]);
                        acc[6 + i] = fmaf(wgt, fmaf(fr, v3.y, v3.x), acc[6 + i]);
                        if (i == 0) {
                            float f = fmaf(e, e, e);
                            r = fmaf(r0, f, r0);
                            peK += cbKB;
                        }
                    }
                }
            }
        }

        cpasync_wait0();
        __syncthreads();
    }

    // Four rotated writes to plane z (disjoint quadrants tiling the image):
    // p at (col x, row y); Rp at (col 511-y, row x); R2p at (511-x, 511-y);
    // R3p at (col y, row 511-x).
    float* P = g_part[z];
    int xm = (NPq - 1) - x;
#pragma unroll
    for (int i = 0; i < 2; i++) {
        int yy = y0 + i;
        int ym = (NPq - 1) - yy;
        P[yy * NPq + x]  = acc[0 + i];
        P[x * NPq + ym]  = acc[2 + i];
        P[ym * NPq + xm] = acc[4 + i];
        P[xm * NPq + yy] = acc[6 + i];
    }
}

// ---------------------------------------------------------------------------
// Launch #5: sum the 4 partial planes + HU normalization.
// ---------------------------------------------------------------------------
__global__ void __launch_bounds__(128) reduce_kernel(float* __restrict__ out) {
    const float A = (float)((Dd * Dd) * (1000.0 / 0.0192) / 4096.0);
    const float B = (float)(24.0 / 4096.0);
    int idx = blockIdx.x * 128 + threadIdx.x;      // float4 index
    float sx = 0.f, sy = 0.f, sz = 0.f, sw = 0.f;
#pragma unroll
    for (int p = 0; p < NPART; p++) {
        float4 v = ((const float4*)g_part[p])[idx];
        sx += v.x; sy += v.y; sz += v.z; sw += v.w;
    }
    float4 o;
    o.x = fmaf(A, sx, B);
    o.y = fmaf(A, sy, B);
    o.z = fmaf(A, sz, B);
    o.w = fmaf(A, sw, B);
    ((float4*)out)[idx] = o;
}

// ---------------------------------------------------------------------------
extern "C" void kernel_launch(void* const* d_in, const int* in_sizes, int n_in,
                              void* d_out, int out_size) {
    const float* sino = (const float*)d_in[0];
    float* out = (float*)d_out;

    cudaFuncSetAttribute(bp_kernel,
                         cudaFuncAttributeMaxDynamicSharedMemorySize, BP_DSMEM);

    filt_kernel<<<1034, 128>>>();           // FILT (1025 blocks) + trig (9)
    hker_kernel<<<NDq, 128>>>();            // spatial filter kernel
    conv_kernel<<<NAq / RB, 256>>>(sino);   // filtered sinogram -> (v, dv)
    dim3 grid(4, 16, SPLIT);                // 64x16 quadrant tiles x 4 splits
    bp_kernel<<<grid, 512, BP_DSMEM>>>();   // <-- 4th launch (profiled slot)
    reduce_kernel<<<NPq * NPq / 4 / 128, 128>>>(out);
}

// round 17
// speedup vs baseline: 1.3589x; 1.0151x over previous
#include <cuda_runtime.h>
#include <cstdint>
#include <math.h>

#define NAq 1152
#define NDq 736
#define NPq 512

#define QANG 288               // base angles; rows a+288j staged per quad-group
#define SPLIT 4
#define APB (QANG / SPLIT)     // 72 quad-groups per bp block
#define CH 2                   // quad-groups per chunk
#define RPC (CH * 4)           // rows per chunk (8)
#define CHP (RPC * NDq)        // float2 per chunk (5888)
#define CHP4 (CHP / 2)         // float4 per chunk (2944)
#define ROW4 (NDq / 2)         // float4 per row (368)
#define BP_DSMEM (2 * CHP * 8) // dynamic smem bytes (94208)
#define NPART SPLIT            // 4 partial planes

// ---- geometry in double (compile-time folded) ----
#define VOXd (1.0 / 0.7)
#define Dd   (VOXd * 595.0)
#define DDd  (VOXd * 490.6)
#define DUd  (VOXd * 1.2858)
#define DSDd (Dd + DDd)

// ---- device scratch (static allocation: allowed) ----
__device__ float  g_filt[1025];
__device__ float  g_hext[1472];          // h[|i-735|] * pi/(2*NA)
__device__ float2 g_trig2[NAq];          // (cos, sin)
__device__ float2 g_fp2[NAq * NDq];      // filtered rows as (v, v_next - v)
__device__ float  g_part[NPART][NPq * NPq];

__device__ __forceinline__ float frcp(float x) {
    float r;
    asm("rcp.approx.f32 %0, %1;" : "=f"(r) : "f"(x));
    return r;
}
__device__ __forceinline__ void cpasync16(unsigned int s, const void* g) {
    asm volatile("cp.async.cg.shared.global [%0], [%1], 16;" :: "r"(s), "l"(g));
}
__device__ __forceinline__ void cpasync_commit() {
    asm volatile("cp.async.commit_group;");
}
__device__ __forceinline__ void cpasync_wait0() {
    asm volatile("cp.async.wait_group 0;");
}

// ---------------------------------------------------------------------------
// Launch #1: FILT[k] (blocks 0..1024) + angle trig (blocks 1025..1033).
// ---------------------------------------------------------------------------
__global__ void __launch_bounds__(128) filt_kernel() {
    int bid = blockIdx.x;
    int tid = threadIdx.x;
    if (bid >= 1025) {
        int a = (bid - 1025) * 128 + tid;        // 9*128 = 1152
        double beta = 2.0 * M_PI * (double)a / (double)NAq + M_PI / 2.0;
        g_trig2[a] = make_float2((float)cos(beta), (float)sin(beta));
        return;
    }
    __shared__ double red[128];
    int k = bid;
    double s = 0.0;
#pragma unroll
    for (int j = 0; j < 4; j++) {
        int m = tid + j * 128;
        int jj = 2 * m + 1;
        float c = cospif((float)((k * jj) & 2047) * (1.0f / 1024.0f));
        s += (double)(c / ((float)jj * (float)jj));
    }
    red[tid] = s;
    __syncthreads();
    for (int w = 64; w > 0; w >>= 1) {
        if (tid < w) red[tid] += red[tid + w];
        __syncthreads();
    }
    if (tid == 0) {
        double four = 0.5 - (4.0 / (M_PI * M_PI)) * red[0];
        if (k > 0) {
            double om = M_PI * (double)k / 2048.0;
            four *= sin(om) / om;
        }
        g_filt[k] = (float)four;
    }
}

// ---------------------------------------------------------------------------
// Launch #2: h[d] = irfft(FILT)[d]. One block per d, 128 threads + reduction.
// ---------------------------------------------------------------------------
__global__ void __launch_bounds__(128) hker_kernel() {
    __shared__ double red[128];
    int d = blockIdx.x;
    int tid = threadIdx.x;
    double s = 0.0;
    for (int k = 1 + tid; k <= 1023; k += 128) {
        s += (double)g_filt[k] * (double)cospif((float)((k * d) & 2047) * (1.0f / 1024.0f));
    }
    red[tid] = s;
    __syncthreads();
    for (int w = 64; w > 0; w >>= 1) {
        if (tid < w) red[tid] += red[tid + w];
        __syncthreads();
    }
    if (tid == 0) {
        double t = (double)g_filt[0] + (double)g_filt[1024] * ((d & 1) ? -1.0 : 1.0)
                 + 2.0 * red[0];
        float h = (float)(t * (1.0 / 2048.0) * (M_PI / (2.0 * (double)NAq)));
        g_hext[735 - d] = h;
        g_hext[735 + d] = h;
    }
}

// ---------------------------------------------------------------------------
// Launch #3: filtering as linear convolution, 4 rows/block; (v, dv) pairs out.
// ---------------------------------------------------------------------------
#define RB 4
__global__ void __launch_bounds__(256) conv_kernel(const float* __restrict__ sino) {
    __shared__ float s_s[RB][NDq];
    __shared__ float s_h[1536];
    int tid = threadIdx.x;
    int row0 = blockIdx.x * RB;
#pragma unroll
    for (int r = 0; r < RB; r++)
        for (int i = tid; i < NDq; i += 256)
            s_s[r][i] = sino[(row0 + r) * NDq + i];
    for (int i = tid; i < 1536; i += 256) s_h[i] = (i < 1471) ? g_hext[i] : 0.0f;
    __syncthreads();

    float acc[RB][3] = {};
    const float* h0 = s_h + tid + 735;
#pragma unroll 4
    for (int k = 0; k < NDq; k++) {
        float hv0 = h0[-k];
        float hv1 = h0[256 - k];
        float hv2 = h0[512 - k];
#pragma unroll
        for (int r = 0; r < RB; r++) {
            float sv = s_s[r][k];
            acc[r][0] = fmaf(sv, hv0, acc[r][0]);
            acc[r][1] = fmaf(sv, hv1, acc[r][1]);
            acc[r][2] = fmaf(sv, hv2, acc[r][2]);
        }
    }
    __syncthreads();
#pragma unroll
    for (int r = 0; r < RB; r++) {
        s_s[r][tid] = acc[r][0];
        s_s[r][tid + 256] = acc[r][1];
        if (tid < NDq - 512) s_s[r][tid + 512] = acc[r][2];
    }
    __syncthreads();
#pragma unroll
    for (int r = 0; r < RB; r++) {
        float2* dst = g_fp2 + (row0 + r) * NDq;
        for (int i = tid; i < NDq; i += 256) {
            float v = s_s[r][i];
            float vn = (i < NDq - 1) ? s_s[r][i + 1] : v;
            dst[i] = make_float2(v, vn - v);
        }
    }
}

// ---------------------------------------------------------------------------
// Launch #4 (PROFILED SLOT): fan-beam backprojection, FULL 4-fold symmetry.
// Quad-group: bases {A, A+288, A+576, A+864}; one (U, frac, weight) serves
// 4 gathers. Paired reciprocals (2 MUFU/quad). cp.async staging offsets
// are chunk-invariant -> hoisted (kills per-chunk integer divisions that
// accounted for ~15M warp-issues in R16's profile).
// Grid (4, 16, 4): quadrant x,y in [256,512), 64x16 tiles, 512 thr, 2 y/thr.
// ---------------------------------------------------------------------------
__global__ void __launch_bounds__(512, 2) bp_kernel() {
    extern __shared__ __align__(16) float2 dsm[];   // 2 chunks x CHP float2
    __shared__ float2 s_tr[2][CH];
    int tid = threadIdx.x;
    int z   = blockIdx.z;
    int w   = tid >> 5;
    int l   = tid & 31;
    int x   = 256 + blockIdx.x * 64 + (w & 1) * 32 + l;
    int y0  = 256 + blockIdx.y * 16 + (w >> 1) * 2;

    float xs  = (float)x  - 255.5f;
    float ys0 = (float)y0 - 255.5f;

    const float Df  = (float)Dd;
    const float Df2 = (float)(Dd * Dd);
    const float Kf  = (float)(DSDd / DUd);

    // per-warp classification (radius bound; identical for all 4 bases)
    int wx0 = 256 + blockIdx.x * 64 + (w & 1) * 32;
    float mx = fmaxf(fabsf((float)wx0 - 255.5f), fabsf((float)wx0 + 31.0f - 255.5f));
    float my = fabsf((float)y0 + 1.0f - 255.5f);
    float rm = sqrtf(mx * mx + my * my);
    bool fast = (Kf * rm) < (366.9f * (Df - rm));

    unsigned int sb0a = (unsigned int)__cvta_generic_to_shared(&dsm[0]);
    unsigned int sb1a = (unsigned int)__cvta_generic_to_shared(&dsm[CHP]);
    int abase = z * APB;

    // ---- hoisted staging pattern (chunk-invariant) ----
    // j-th transfer: idx = tid + j*512 (valid while < CHP4);
    // r = idx/ROW4 (smem row), o = idx%ROW4 (float4 within row);
    // source row (relative to gbase) = (r>>2) + (r&3)*QANG.
    int goff[6];        // float2 offset into g_fp2 relative to gbase*NDq
    unsigned soff[6];   // byte offset into chunk smem
    bool jval[6];
#pragma unroll
    for (int j = 0; j < 6; j++) {
        int idx = tid + j * 512;
        jval[j] = (idx < CHP4);
        int r = idx / ROW4;          // compile-time-hoisted per thread (once)
        int o = idx - r * ROW4;
        goff[j] = ((r >> 2) + (r & 3) * QANG) * NDq + o * 2;
        soff[j] = (unsigned)idx * 16u;
    }

    // preload chunk 0
    {
        const float2* srcb = g_fp2 + abase * NDq;
#pragma unroll
        for (int j = 0; j < 6; j++)
            if (jval[j]) cpasync16(sb0a + soff[j], srcb + goff[j]);
    }
    if (tid < CH) s_tr[0][tid] = g_trig2[abase + tid];
    cpasync_commit();
    cpasync_wait0();
    __syncthreads();

    float acc[8];                                    // [partner*2 + i]
#pragma unroll
    for (int i = 0; i < 8; i++) acc[i] = 0.0f;

    const int NCHb = APB / CH;                       // 36
    const float2* srcb = g_fp2 + (abase + CH) * NDq; // next-chunk base
    for (int c = 0; c < NCHb; c++) {
        if (c + 1 < NCHb) {
            unsigned int dsts = (c & 1) ? sb0a : sb1a;
#pragma unroll
            for (int j = 0; j < 6; j++)
                if (jval[j]) cpasync16(dsts + soff[j], srcb + goff[j]);
            if (tid < CH) s_tr[(c + 1) & 1][tid] = g_trig2[abase + (c + 1) * CH + tid];
            srcb += CH * NDq;
        }
        cpasync_commit();

        const float2* buf = (c & 1) ? (dsm + CHP) : dsm;

#pragma unroll
        for (int g = 0; g < CH; g++) {
            float2 t2 = s_tr[c & 1][g];
            float cb = t2.x, sb = t2.y;
            const float2* rowg = buf + (g * 4) * NDq - 2;

            // shared geometry for the quad: pd = pdot(A,p), pq = pe(A,p)
            float pd  = fmaf(xs, cb, ys0 * sb);
            float pq  = fmaf(ys0, cb, -xs * sb);
            float pdK = pd * Kf;
            float pqK = pq * Kf;
            float cbK = cb * Kf, sbK = sb * Kf;
            // paired reciprocals: 2 MUFU serve all 4 bases
            float inv02 = frcp(fmaf(pd, -pd, Df2));
            float inv13 = frcp(fmaf(pq, -pq, Df2));

#pragma unroll
            for (int b = 0; b < 4; b++) {
                float peK  = (b == 0) ? pqK : (b == 1) ? -pdK
                           : (b == 2) ? -pqK : pdK;
                float cbKB = (b == 0) ? cbK : (b == 1) ? -sbK
                           : (b == 2) ? -cbK : sbK;         // d(peK)/dy
                float sbB  = (b == 0) ? sb : (b == 1) ? cb
                           : (b == 2) ? -sb : -cb;          // d(den)/dy = -sbB
                float r0   = (b == 0) ? (Df + pd) * inv02
                           : (b == 1) ? (Df + pq) * inv13
                           : (b == 2) ? (Df - pd) * inv02
                           :            (Df - pq) * inv13;  // 1/den_b
                float e  = sbB * r0;
                float r  = r0;
                const int o0 = ((b + 0) & 3) * NDq;
                const int o1 = ((b + 1) & 3) * NDq;
                const int o2 = ((b + 2) & 3) * NDq;
                const int o3 = ((b + 3) & 3) * NDq;

                if (fast) {
#pragma unroll
                    for (int i = 0; i < 2; i++) {
                        float U  = fmaf(peK, r, 369.5f);     // iu+2 in (2.6,736.4)
                        float M  = U + 8388607.5f;
                        int   n  = __float_as_int(M) & 0x3FF;
                        float fr = U - (M - 8388608.0f);
                        float wgt = r * r;
                        float2 v0 = rowg[n + o0];
                        float2 v1 = rowg[n + o1];
                        float2 v2 = rowg[n + o2];
                        float2 v3 = rowg[n + o3];
                        acc[0 + i] = fmaf(wgt, fmaf(fr, v0.y, v0.x), acc[0 + i]);
                        acc[2 + i] = fmaf(wgt, fmaf(fr, v1.y, v1.x), acc[2 + i]);
                        acc[4 + i] = fmaf(wgt, fmaf(fr, v2.y, v2.x), acc[4 + i]);
                        acc[6 + i] = fmaf(wgt, fmaf(fr, v3.y, v3.x), acc[6 + i]);
                        if (i == 0) {                        // advance dy=1
                            float f = fmaf(e, e, e);         // t + t^2
                            r = fmaf(r0, f, r0);
                            peK += cbKB;
                        }
                    }
                } else {
#pragma unroll
                    for (int i = 0; i < 2; i++) {
                        float U  = fmaf(peK, r, 369.5f);
                        float Uc = fminf(fmaxf(U, 2.0f), 736.999f);
                        float M  = Uc + 8388607.5f;
                        int   n  = __float_as_int(M) & 0x3FF;  // [2, 736]
                        float fr = Uc - (M - 8388608.0f);
                        bool  ok = (U >= 2.0f) && (U < 737.0f);
                        float wgt = ok ? r * r : 0.0f;
                        float2 v0 = rowg[n + o0];
                        float2 v1 = rowg[n + o1];
                        float2 v2 = rowg[n + o2];
                        float2 v3 = rowg[n + o3];
                        acc[0 + i] = fmaf(wgt, fmaf(fr, v0.y, v0.x), acc[0 + i]);
                        acc[2 + i] = fmaf(wgt, fmaf(fr, v1.y, v1.x), acc[2 + i]);
                        acc[4 + i] = fmaf(wgt, fmaf(fr, v2.y, v2.x), acc[4 + i]);
                        acc[6 + i] = fmaf(wgt, fmaf(fr, v3.y, v3.x), acc[6 + i]);
                        if (i == 0) {
                            float f = fmaf(e, e, e);
                            r = fmaf(r0, f, r0);
                            peK += cbKB;
                        }
                    }
                }
            }
        }

        cpasync_wait0();
        __syncthreads();
    }

    // Four rotated writes to plane z (disjoint quadrants tiling the image).
    float* P = g_part[z];
    int xm = (NPq - 1) - x;
#pragma unroll
    for (int i = 0; i < 2; i++) {
        int yy = y0 + i;
        int ym = (NPq - 1) - yy;
        P[yy * NPq + x]  = acc[0 + i];
        P[x * NPq + ym]  = acc[2 + i];
        P[ym * NPq + xm] = acc[4 + i];
        P[xm * NPq + yy] = acc[6 + i];
    }
}

// ---------------------------------------------------------------------------
// Launch #5: sum the 4 partial planes + HU normalization.
// ---------------------------------------------------------------------------
__global__ void __launch_bounds__(128) reduce_kernel(float* __restrict__ out) {
    const float A = (float)((Dd * Dd) * (1000.0 / 0.0192) / 4096.0);
    const float B = (float)(24.0 / 4096.0);
    int idx = blockIdx.x * 128 + threadIdx.x;      // float4 index
    float sx = 0.f, sy = 0.f, sz = 0.f, sw = 0.f;
#pragma unroll
    for (int p = 0; p < NPART; p++) {
        float4 v = ((const float4*)g_part[p])[idx];
        sx += v.x; sy += v.y; sz += v.z; sw += v.w;
    }
    float4 o;
    o.x = fmaf(A, sx, B);
    o.y = fmaf(A, sy, B);
    o.z = fmaf(A, sz, B);
    o.w = fmaf(A, sw, B);
    ((float4*)out)[idx] = o;
}

// ---------------------------------------------------------------------------
extern "C" void kernel_launch(void* const* d_in, const int* in_sizes, int n_in,
                              void* d_out, int out_size) {
    const float* sino = (const float*)d_in[0];
    float* out = (float*)d_out;

    cudaFuncSetAttribute(bp_kernel,
                         cudaFuncAttributeMaxDynamicSharedMemorySize, BP_DSMEM);

    filt_kernel<<<1034, 128>>>();           // FILT (1025 blocks) + trig (9)
    hker_kernel<<<NDq, 128>>>();            // spatial filter kernel
    conv_kernel<<<NAq / RB, 256>>>(sino);   // filtered sinogram -> (v, dv)
    dim3 grid(4, 16, SPLIT);                // 64x16 quadrant tiles x 4 splits
    bp_kernel<<<grid, 512, BP_DSMEM>>>();   // <-- 4th launch (profiled slot)
    reduce_kernel<<<NPq * NPq / 4 / 128, 128>>>(out);
}